// round 14
// baseline (speedup 1.0000x reference)
#include <cuda_runtime.h>
#include <math.h>
#include <stdint.h>

#define B_ 2
#define S_ 4096
#define D_ 768
#define H_ 12
#define DK_ 64

// scratch (no cudaMalloc allowed)
__device__ float g_Q[(size_t)B_ * S_ * D_];
__device__ float g_K[(size_t)B_ * S_ * D_];
__device__ float g_V[(size_t)B_ * S_ * D_];
__device__ float g_AO[(size_t)B_ * S_ * D_];
__device__ float g_T[(size_t)3 * B_ * S_ * D_];   // pre-rounded inputs
__device__ float g_W4[(size_t)4 * D_ * D_];       // pre-rounded weights
__device__ float g_L[(size_t)B_ * H_ * S_];       // softmax row sums

__device__ __forceinline__ uint32_t f2tf(float x) {
    uint32_t u;
    asm("cvt.rna.tf32.f32 %0, %1;" : "=r"(u) : "f"(x));
    return u;
}

__device__ __forceinline__ void mma8(float* c, const uint32_t* a,
                                     uint32_t b0, uint32_t b1) {
    asm volatile(
        "mma.sync.aligned.m16n8k8.row.col.f32.tf32.tf32.f32 "
        "{%0,%1,%2,%3}, {%4,%5,%6,%7}, {%8,%9}, {%0,%1,%2,%3};"
        : "+f"(c[0]), "+f"(c[1]), "+f"(c[2]), "+f"(c[3])
        : "r"(a[0]), "r"(a[1]), "r"(a[2]), "r"(a[3]), "r"(b0), "r"(b1));
}

__device__ __forceinline__ void cpa16(uint32_t saddr, const void* g) {
    asm volatile("cp.async.cg.shared.global [%0], [%1], 16;"
                 :: "r"(saddr), "l"(g));
}
__device__ __forceinline__ uint32_t cvs(const void* p) {
    return (uint32_t)__cvta_generic_to_shared(p);
}
#define CPCOMMIT asm volatile("cp.async.commit_group;")
#define CPWAIT0  asm volatile("cp.async.wait_group 0;")

// ---------------------------------------------------------------------------
// batched elementwise pre-round to tf32 (rna); grid.y selects tensor
// ---------------------------------------------------------------------------
__global__ void preround3(const float* __restrict__ s0,
                          const float* __restrict__ s1,
                          const float* __restrict__ s2,
                          float* __restrict__ dst, int n4) {
    int i = blockIdx.x * blockDim.x + threadIdx.x;
    if (i >= n4) return;
    const float* src = (blockIdx.y == 0) ? s0 : (blockIdx.y == 1) ? s1 : s2;
    float4 v = ((const float4*)src)[i];
    uint4 u;
    u.x = f2tf(v.x); u.y = f2tf(v.y); u.z = f2tf(v.z); u.w = f2tf(v.w);
    ((uint4*)(dst + (size_t)blockIdx.y * n4 * 4))[i] = u;
}

__global__ void preround4(const float* __restrict__ s0,
                          const float* __restrict__ s1,
                          const float* __restrict__ s2,
                          const float* __restrict__ s3,
                          float* __restrict__ dst, int n4) {
    int i = blockIdx.x * blockDim.x + threadIdx.x;
    if (i >= n4) return;
    const float* src = (blockIdx.y == 0) ? s0 : (blockIdx.y == 1) ? s1
                     : (blockIdx.y == 2) ? s2 : s3;
    float4 v = ((const float4*)src)[i];
    uint4 u;
    u.x = f2tf(v.x); u.y = f2tf(v.y); u.z = f2tf(v.z); u.w = f2tf(v.w);
    ((uint4*)(dst + (size_t)blockIdx.y * n4 * 4))[i] = u;
}

// ---------------------------------------------------------------------------
// Fused QKV TC GEMM (R13): grid.z selects (input, weight, bias, output).
// 128x64 tile, 8 warps (4m x 2n), cp.async double-buffered, k-tile 64.
// ---------------------------------------------------------------------------
__global__ void __launch_bounds__(256) gemm_qkv(
        const float* __restrict__ T, const float* __restrict__ W4,
        const float* __restrict__ bq, const float* __restrict__ bk,
        const float* __restrict__ bv,
        float* __restrict__ Qp, float* __restrict__ Kp, float* __restrict__ Vp) {
    extern __shared__ float sg[];
    float* Asb[2] = { sg,          sg + 8704 };            // 128*68 each
    float* Wsb[2] = { sg + 17408,  sg + 17408 + 4352 };    // 64*68 each

    const int M = B_ * S_, N = D_, K = D_;
    const int z = blockIdx.z;
    const float* A = T + (size_t)z * M * K;
    const float* W = W4 + (size_t)z * N * K;
    const float* bias = (z == 0) ? bq : (z == 1) ? bk : bv;
    float* C = (z == 0) ? Qp : (z == 1) ? Kp : Vp;

    const int tid = threadIdx.x, lane = tid & 31, w = tid >> 5;
    const int mw = w >> 1, nw = w & 1, g = lane >> 2, t = lane & 3;
    const int m0 = blockIdx.x * 128, n0 = blockIdx.y * 64;

    float acc[2][4][4] = {};

#define GSTAGE(k0, bufi)                                                       \
    {                                                                          \
        _Pragma("unroll")                                                      \
        for (int r = 0; r < 8; r++) {                                          \
            int idx = tid + r * 256, rr = idx >> 4, cc = idx & 15;             \
            cpa16(cvs(&Asb[bufi][rr * 68 + cc * 4]),                           \
                  &A[(size_t)(m0 + rr) * K + (k0) + cc * 4]);                  \
        }                                                                      \
        _Pragma("unroll")                                                      \
        for (int r = 0; r < 4; r++) {                                          \
            int idx = tid + r * 256, rr = idx >> 4, cc = idx & 15;             \
            cpa16(cvs(&Wsb[bufi][rr * 68 + cc * 4]),                           \
                  &W[(size_t)(n0 + rr) * K + (k0) + cc * 4]);                  \
        }                                                                      \
    }

    GSTAGE(0, 0); CPCOMMIT;
    const int NT = K / 64;
    for (int kt = 0; kt < NT; kt++) {
        CPWAIT0;
        __syncthreads();
        if (kt + 1 < NT) { GSTAGE((kt + 1) * 64, (kt + 1) & 1); CPCOMMIT; }
        const uint32_t* Au = (const uint32_t*)Asb[kt & 1];
        const uint32_t* Wu = (const uint32_t*)Wsb[kt & 1];
#pragma unroll
        for (int k8 = 0; k8 < 8; k8++) {
            uint32_t a[2][4];
#pragma unroll
            for (int mm = 0; mm < 2; mm++) {
                int ar = (mw * 32 + mm * 16 + g) * 68 + t + 8 * k8;
                a[mm][0] = Au[ar];     a[mm][1] = Au[ar + 8 * 68];
                a[mm][2] = Au[ar + 4]; a[mm][3] = Au[ar + 8 * 68 + 4];
            }
#pragma unroll
            for (int nf = 0; nf < 4; nf++) {
                int br = (nw * 32 + nf * 8 + g) * 68 + t + 8 * k8;
                uint32_t b0 = Wu[br], b1 = Wu[br + 4];
                mma8(acc[0][nf], a[0], b0, b1);
                mma8(acc[1][nf], a[1], b0, b1);
            }
        }
    }

    const float sc = (z == 0) ? 0.125f : 1.0f;
#pragma unroll
    for (int mm = 0; mm < 2; mm++) {
        int mrow = m0 + mw * 32 + mm * 16 + g;
#pragma unroll
        for (int nf = 0; nf < 4; nf++) {
            int n = n0 + nw * 32 + nf * 8 + 2 * t;
            float b0 = bias[n], b1 = bias[n + 1];
            float v0 = __uint_as_float(f2tf((acc[mm][nf][0] + b0) * sc));
            float v1 = __uint_as_float(f2tf((acc[mm][nf][1] + b1) * sc));
            float v2 = __uint_as_float(f2tf((acc[mm][nf][2] + b0) * sc));
            float v3 = __uint_as_float(f2tf((acc[mm][nf][3] + b1) * sc));
            *(float2*)&C[(size_t)mrow * N + n] = make_float2(v0, v1);
            *(float2*)&C[(size_t)(mrow + 8) * N + n] = make_float2(v2, v3);
        }
    }
}

// ---------------------------------------------------------------------------
// O-projection GEMM (raw fp32 out, streaming store): identical inner loop.
// ---------------------------------------------------------------------------
__global__ void __launch_bounds__(256) gemm_o(const float* __restrict__ A,
                                              const float* __restrict__ W,
                                              const float* __restrict__ bias,
                                              float* __restrict__ C,
                                              int M, int N, int K) {
    extern __shared__ float sg[];
    float* Asb[2] = { sg,          sg + 8704 };
    float* Wsb[2] = { sg + 17408,  sg + 17408 + 4352 };

    const int tid = threadIdx.x, lane = tid & 31, w = tid >> 5;
    const int mw = w >> 1, nw = w & 1, g = lane >> 2, t = lane & 3;
    const int m0 = blockIdx.x * 128, n0 = blockIdx.y * 64;

    float acc[2][4][4] = {};

    GSTAGE(0, 0); CPCOMMIT;
    const int NT = K / 64;
    for (int kt = 0; kt < NT; kt++) {
        CPWAIT0;
        __syncthreads();
        if (kt + 1 < NT) { GSTAGE((kt + 1) * 64, (kt + 1) & 1); CPCOMMIT; }
        const uint32_t* Au = (const uint32_t*)Asb[kt & 1];
        const uint32_t* Wu = (const uint32_t*)Wsb[kt & 1];
#pragma unroll
        for (int k8 = 0; k8 < 8; k8++) {
            uint32_t a[2][4];
#pragma unroll
            for (int mm = 0; mm < 2; mm++) {
                int ar = (mw * 32 + mm * 16 + g) * 68 + t + 8 * k8;
                a[mm][0] = Au[ar];     a[mm][1] = Au[ar + 8 * 68];
                a[mm][2] = Au[ar + 4]; a[mm][3] = Au[ar + 8 * 68 + 4];
            }
#pragma unroll
            for (int nf = 0; nf < 4; nf++) {
                int br = (nw * 32 + nf * 8 + g) * 68 + t + 8 * k8;
                uint32_t b0 = Wu[br], b1 = Wu[br + 4];
                mma8(acc[0][nf], a[0], b0, b1);
                mma8(acc[1][nf], a[1], b0, b1);
            }
        }
    }

#pragma unroll
    for (int mm = 0; mm < 2; mm++) {
        int mrow = m0 + mw * 32 + mm * 16 + g;
#pragma unroll
        for (int nf = 0; nf < 4; nf++) {
            int n = n0 + nw * 32 + nf * 8 + 2 * t;
            float b0 = bias[n], b1 = bias[n + 1];
            __stcs((float2*)&C[(size_t)mrow * N + n],
                   make_float2(acc[mm][nf][0] + b0, acc[mm][nf][1] + b1));
            __stcs((float2*)&C[(size_t)(mrow + 8) * N + n],
                   make_float2(acc[mm][nf][2] + b0, acc[mm][nf][3] + b1));
        }
    }
}

// ---------------------------------------------------------------------------
// Attention pass 1: rowsums of exp(scores) -> g_L.
// 4m x 2n warp layout: qa = 32 regs/warp -> ~70 regs total -> 3 blocks/SM.
// No per-tile Q reloads (register-resident A fragments).
// ---------------------------------------------------------------------------
#define STRK 68
#define STRV 72

__global__ void __launch_bounds__(256, 3)
attn_p1(const float* __restrict__ Qg, const float* __restrict__ Kg,
        float* __restrict__ gL) {
    extern __shared__ float sm[];
    float* Ksb[2] = { sm, sm + 64 * STRK };
    float* Qs = sm + 2 * 64 * STRK;            // 64*68
    float* Ls = Qs + 64 * STRK;                // 128 floats
    const uint32_t* Qu = (const uint32_t*)Qs;

    const int tid = threadIdx.x, lane = tid & 31, w = tid >> 5;
    const int mw = w & 3, nw = w >> 2, g = lane >> 2, t = lane & 3;
    const int q0 = blockIdx.x * 64, h = blockIdx.y, b = blockIdx.z;
    const size_t qbase = ((size_t)b * S_ + q0) * D_ + h * DK_;
    const size_t kvbase = (size_t)b * S_ * D_ + h * DK_;

#define KSTAGE1(jt, bufi)                                                      \
    {                                                                          \
        _Pragma("unroll")                                                      \
        for (int r = 0; r < 4; r++) {                                          \
            int idx = tid + r * 256, rr = idx >> 4, cc = idx & 15;             \
            cpa16(cvs(&Ksb[bufi][rr * STRK + cc * 4]),                         \
                  &Kg[kvbase + (size_t)((jt) * 64 + rr) * D_ + cc * 4]);       \
        }                                                                      \
    }

    // stage Q (tf32, 0.125-prescaled)
#pragma unroll
    for (int r = 0; r < 4; r++) {
        int idx = tid + r * 256, rr = idx >> 4, cc = idx & 15;
        *(float4*)&Qs[rr * STRK + cc * 4] =
            *(const float4*)&Qg[qbase + (size_t)rr * D_ + cc * 4];
    }
    KSTAGE1(0, 0); CPCOMMIT;
    __syncthreads();

    // register-resident Q fragments: one m16 strip per warp (32 regs)
    uint32_t qa[8][4];
    {
        int ar = (mw * 16 + g) * STRK + t;
#pragma unroll
        for (int k8 = 0; k8 < 8; k8++) {
            qa[k8][0] = Qu[ar + 8 * k8];
            qa[k8][1] = Qu[ar + 8 * STRK + 8 * k8];
            qa[k8][2] = Qu[ar + 4 + 8 * k8];
            qa[k8][3] = Qu[ar + 8 * STRK + 4 + 8 * k8];
        }
    }

    float ls0 = 0.f, ls1 = 0.f;
    const int NT = S_ / 64;
    for (int jt = 0; jt < NT; jt++) {
        CPWAIT0;
        __syncthreads();
        if (jt + 1 < NT) { KSTAGE1(jt + 1, (jt + 1) & 1); CPCOMMIT; }
        const uint32_t* Ku = (const uint32_t*)Ksb[jt & 1];
        float c[4][4] = {};
#pragma unroll
        for (int k8 = 0; k8 < 8; k8++) {
#pragma unroll
            for (int nf = 0; nf < 4; nf++) {
                int br = (nw * 32 + nf * 8 + g) * STRK + t + 8 * k8;
                mma8(c[nf], qa[k8], Ku[br], Ku[br + 4]);
            }
        }
#pragma unroll
        for (int nf = 0; nf < 4; nf++) {
            ls0 += __expf(c[nf][0]) + __expf(c[nf][1]);
            ls1 += __expf(c[nf][2]) + __expf(c[nf][3]);
        }
    }
    ls0 += __shfl_xor_sync(~0u, ls0, 1); ls0 += __shfl_xor_sync(~0u, ls0, 2);
    ls1 += __shfl_xor_sync(~0u, ls1, 1); ls1 += __shfl_xor_sync(~0u, ls1, 2);
    if (t == 0) {
        Ls[nw * 64 + mw * 16 + g]     = ls0;
        Ls[nw * 64 + mw * 16 + 8 + g] = ls1;
    }
    __syncthreads();
    if (tid < 64) {
        gL[((size_t)(b * H_ + h) * S_) + q0 + tid] = Ls[tid] + Ls[64 + tid];
    }
}

// ---------------------------------------------------------------------------
// Attention pass 2 — R13 pass-2 VERBATIM (register qa, double-buffered K+V,
// PT round-trip, __stcs P stores), linv read from g_L.
// ---------------------------------------------------------------------------
__global__ void __launch_bounds__(256, 2)
attn_p2(const float* __restrict__ Qg, const float* __restrict__ Kg,
        const float* __restrict__ Vg, const float* __restrict__ gL,
        float* __restrict__ Pout, float* __restrict__ Oout) {
    extern __shared__ float sm[];
    float* Ksb[2] = { sm,                 sm + 64 * STRK };
    float* Vsb[2] = { sm + 2 * 64 * STRK, sm + 2 * 64 * STRK + 64 * STRV };
    float* Qs = sm + 2 * 64 * STRK + 2 * 64 * STRV;  // 4608 floats (Q / PT)
    uint2* PT = (uint2*)Qs;
    const uint32_t* Qu = (const uint32_t*)Qs;

    const int tid = threadIdx.x, lane = tid & 31, w = tid >> 5;
    const int mw = w & 1, nw = w >> 1, g = lane >> 2, t = lane & 3;
    const int q0 = blockIdx.x * 64, h = blockIdx.y, b = blockIdx.z;
    const size_t qbase = ((size_t)b * S_ + q0) * D_ + h * DK_;
    const size_t kvbase = (size_t)b * S_ * D_ + h * DK_;

#define KSTAGE(jt, bufi)                                                       \
    {                                                                          \
        _Pragma("unroll")                                                      \
        for (int r = 0; r < 4; r++) {                                          \
            int idx = tid + r * 256, rr = idx >> 4, cc = idx & 15;             \
            cpa16(cvs(&Ksb[bufi][rr * STRK + cc * 4]),                         \
                  &Kg[kvbase + (size_t)((jt) * 64 + rr) * D_ + cc * 4]);       \
        }                                                                      \
    }
#define VSTAGE(jt, bufi)                                                       \
    {                                                                          \
        _Pragma("unroll")                                                      \
        for (int r = 0; r < 4; r++) {                                          \
            int idx = tid + r * 256, rr = idx >> 4, cc = idx & 15;             \
            cpa16(cvs(&Vsb[bufi][rr * STRV + cc * 4]),                         \
                  &Vg[kvbase + (size_t)((jt) * 64 + rr) * D_ + cc * 4]);       \
        }                                                                      \
    }

    // stage Q; prefetch tile 0
#pragma unroll
    for (int r = 0; r < 4; r++) {
        int idx = tid + r * 256, rr = idx >> 4, cc = idx & 15;
        *(float4*)&Qs[rr * 68 + cc * 4] =
            *(const float4*)&Qg[qbase + (size_t)rr * D_ + cc * 4];
    }
    KSTAGE(0, 0); VSTAGE(0, 0); CPCOMMIT;
    __syncthreads();
    uint32_t qa[2][8][4];
#pragma unroll
    for (int mm = 0; mm < 2; mm++) {
        int ar = (mw * 32 + mm * 16 + g) * 68 + t;
#pragma unroll
        for (int k8 = 0; k8 < 8; k8++) {
            qa[mm][k8][0] = Qu[ar + 8 * k8];
            qa[mm][k8][1] = Qu[ar + 8 * 68 + 8 * k8];
            qa[mm][k8][2] = Qu[ar + 4 + 8 * k8];
            qa[mm][k8][3] = Qu[ar + 8 * 68 + 4 + 8 * k8];
        }
    }

    const size_t lbase = (size_t)(b * H_ + h) * S_ + q0;
    float linv[2][2];
#pragma unroll
    for (int mm = 0; mm < 2; mm++) {
        linv[mm][0] = 1.f / gL[lbase + mw * 32 + mm * 16 + g];
        linv[mm][1] = 1.f / gL[lbase + mw * 32 + mm * 16 + 8 + g];
    }

    float out[2][2][4] = {};
    const int NT = S_ / 64;
    for (int jt = 0; jt < NT; jt++) {
        CPWAIT0;
        __syncthreads();   // also protects Qs->PT reuse (qa loaded above)
        if (jt + 1 < NT) {
            KSTAGE(jt + 1, (jt + 1) & 1); VSTAGE(jt + 1, (jt + 1) & 1); CPCOMMIT;
        }
        const uint32_t* Ku = (const uint32_t*)Ksb[jt & 1];
        const uint32_t* Vu = (const uint32_t*)Vsb[jt & 1];
        float c[2][2][4] = {};
#pragma unroll
        for (int k8 = 0; k8 < 8; k8++) {
#pragma unroll
            for (int nf = 0; nf < 2; nf++) {
                int br = (nw * 16 + nf * 8 + g) * STRK + t + 8 * k8;
                uint32_t b0 = Ku[br], b1 = Ku[br + 4];
                mma8(c[0][nf], qa[0][k8], b0, b1);
                mma8(c[1][nf], qa[1][k8], b0, b1);
            }
        }
        // normalized P -> gmem (streaming); tf32 P -> transposed smem tile
#pragma unroll
        for (int mm = 0; mm < 2; mm++) {
            int rowg = mw * 32 + mm * 16 + g;
            int pi = 16 * mw + 8 * mm + g;
            size_t gp = ((size_t)(b * H_ + h) * S_ + (q0 + rowg)) * S_ +
                        jt * 64 + nw * 16 + 2 * t;
#pragma unroll
            for (int nf = 0; nf < 2; nf++) {
                float p0 = __expf(c[mm][nf][0]) * linv[mm][0];
                float p1 = __expf(c[mm][nf][1]) * linv[mm][0];
                float p2 = __expf(c[mm][nf][2]) * linv[mm][1];
                float p3 = __expf(c[mm][nf][3]) * linv[mm][1];
                __stcs((float2*)&Pout[gp + nf * 8], make_float2(p0, p1));
                __stcs((float2*)&Pout[gp + nf * 8 + (size_t)8 * S_],
                       make_float2(p2, p3));
                int c0 = nw * 16 + nf * 8 + 2 * t;
                PT[c0 * 36 + pi] = make_uint2(f2tf(p0), f2tf(p2));
                PT[(c0 + 1) * 36 + pi] = make_uint2(f2tf(p1), f2tf(p3));
            }
        }
        __syncthreads();
        // P @ V (pa via conflict-free LDS64)
#pragma unroll
        for (int k8 = 0; k8 < 8; k8++) {
            int ca = t + 8 * k8, cb = ca + 4;
            uint2 u0 = PT[ca * 36 + 16 * mw + g];
            uint2 u1 = PT[cb * 36 + 16 * mw + g];
            uint2 u2 = PT[ca * 36 + 16 * mw + 8 + g];
            uint2 u3 = PT[cb * 36 + 16 * mw + 8 + g];
            uint32_t pa0[4] = { u0.x, u0.y, u1.x, u1.y };
            uint32_t pa1[4] = { u2.x, u2.y, u3.x, u3.y };
#pragma unroll
            for (int nf = 0; nf < 2; nf++) {
                int n = nw * 16 + nf * 8 + g;
                uint32_t b0 = Vu[(8 * k8 + t) * STRV + n];
                uint32_t b1 = Vu[(8 * k8 + t + 4) * STRV + n];
                mma8(out[0][nf], pa0, b0, b1);
                mma8(out[1][nf], pa1, b0, b1);
            }
        }
        __syncthreads();
    }

    // epilogue: AO in [B,S,D], tf32-rounded for the O-GEMM
#pragma unroll
    for (int mm = 0; mm < 2; mm++) {
        int row = q0 + mw * 32 + mm * 16 + g;
#pragma unroll
        for (int nf = 0; nf < 2; nf++) {
            int dk = h * DK_ + nw * 16 + nf * 8 + 2 * t;
            *(float2*)&Oout[((size_t)b * S_ + row) * D_ + dk] =
                make_float2(__uint_as_float(f2tf(out[mm][nf][0])),
                            __uint_as_float(f2tf(out[mm][nf][1])));
            *(float2*)&Oout[((size_t)b * S_ + row + 8) * D_ + dk] =
                make_float2(__uint_as_float(f2tf(out[mm][nf][2])),
                            __uint_as_float(f2tf(out[mm][nf][3])));
        }
    }
}

// ---------------------------------------------------------------------------
extern "C" void kernel_launch(void* const* d_in, const int* in_sizes, int n_in,
                              void* d_out, int out_size) {
    const float* query = (const float*)d_in[0];
    const float* key   = (const float*)d_in[1];
    const float* value = (const float*)d_in[2];
    const float* Wq = (const float*)d_in[3];
    const float* bq = (const float*)d_in[4];
    const float* Wk = (const float*)d_in[5];
    const float* bk = (const float*)d_in[6];
    const float* Wv = (const float*)d_in[7];
    const float* bv = (const float*)d_in[8];
    const float* Wo = (const float*)d_in[9];
    const float* bo = (const float*)d_in[10];

    float* out_main = (float*)d_out;
    float* out_attn = (float*)d_out + (size_t)B_ * S_ * D_;

    float* Qp;  cudaGetSymbolAddress((void**)&Qp, g_Q);
    float* Kp;  cudaGetSymbolAddress((void**)&Kp, g_K);
    float* Vp;  cudaGetSymbolAddress((void**)&Vp, g_V);
    float* AOp; cudaGetSymbolAddress((void**)&AOp, g_AO);
    float* Tp;  cudaGetSymbolAddress((void**)&Tp, g_T);
    float* Wp;  cudaGetSymbolAddress((void**)&Wp, g_W4);
    float* Lp;  cudaGetSymbolAddress((void**)&Lp, g_L);

    const size_t NX = (size_t)B_ * S_ * D_;   // 6291456
    const size_t NW = (size_t)D_ * D_;        // 589824

    preround3<<<dim3((int)(NX / 4 + 255) / 256, 3), 256>>>(
        query, key, value, Tp, (int)(NX / 4));
    preround4<<<dim3((int)(NW / 4 + 255) / 256, 4), 256>>>(
        Wq, Wk, Wv, Wo, Wp, (int)(NW / 4));

    const int M = B_ * S_;
    const int gsmem = (2 * 8704 + 2 * 4352) * 4;   // 104448 B
    cudaFuncSetAttribute(gemm_qkv,
                         cudaFuncAttributeMaxDynamicSharedMemorySize, gsmem);
    cudaFuncSetAttribute(gemm_o,
                         cudaFuncAttributeMaxDynamicSharedMemorySize, gsmem);
    const int p1smem = (2 * 64 * STRK + 64 * STRK + 128) * 4;          // 52736 B
    cudaFuncSetAttribute(attn_p1,
                         cudaFuncAttributeMaxDynamicSharedMemorySize, p1smem);
    const int p2smem = (2 * 64 * STRK + 2 * 64 * STRV + 4608) * 4;     // 90112 B
    cudaFuncSetAttribute(attn_p2,
                         cudaFuncAttributeMaxDynamicSharedMemorySize, p2smem);

    gemm_qkv<<<dim3(M / 128, D_ / 64, 3), 256, gsmem>>>(
        Tp, Wp, bq, bk, bv, Qp, Kp, Vp);

    attn_p1<<<dim3(S_ / 64, H_, B_), 256, p1smem>>>(Qp, Kp, Lp);
    attn_p2<<<dim3(S_ / 64, H_, B_), 256, p2smem>>>(Qp, Kp, Vp, Lp,
                                                    out_attn, AOp);

    gemm_o<<<dim3(M / 128, D_ / 64), 256, gsmem>>>(
        AOp, Wp + 3 * NW, bo, out_main, M, D_, D_);
}

// round 15
// speedup vs baseline: 1.1368x; 1.1368x over previous
#include <cuda_runtime.h>
#include <math.h>
#include <stdint.h>

#define B_ 2
#define S_ 4096
#define D_ 768
#define H_ 12
#define DK_ 64

// scratch (no cudaMalloc allowed)
__device__ float g_Q[(size_t)B_ * S_ * D_];
__device__ float g_K[(size_t)B_ * S_ * D_];
__device__ float g_V[(size_t)B_ * S_ * D_];
__device__ float g_AO[(size_t)B_ * S_ * D_];
__device__ float g_T[(size_t)3 * B_ * S_ * D_];   // pre-rounded inputs
__device__ float g_W4[(size_t)4 * D_ * D_];       // pre-rounded weights

__device__ __forceinline__ uint32_t f2tf(float x) {
    uint32_t u;
    asm("cvt.rna.tf32.f32 %0, %1;" : "=r"(u) : "f"(x));
    return u;
}

__device__ __forceinline__ void mma8(float* c, const uint32_t* a,
                                     uint32_t b0, uint32_t b1) {
    asm volatile(
        "mma.sync.aligned.m16n8k8.row.col.f32.tf32.tf32.f32 "
        "{%0,%1,%2,%3}, {%4,%5,%6,%7}, {%8,%9}, {%0,%1,%2,%3};"
        : "+f"(c[0]), "+f"(c[1]), "+f"(c[2]), "+f"(c[3])
        : "r"(a[0]), "r"(a[1]), "r"(a[2]), "r"(a[3]), "r"(b0), "r"(b1));
}

__device__ __forceinline__ void cpa16(uint32_t saddr, const void* g) {
    asm volatile("cp.async.cg.shared.global [%0], [%1], 16;"
                 :: "r"(saddr), "l"(g));
}
__device__ __forceinline__ uint32_t cvs(const void* p) {
    return (uint32_t)__cvta_generic_to_shared(p);
}
#define CPCOMMIT asm volatile("cp.async.commit_group;")
#define CPWAIT0  asm volatile("cp.async.wait_group 0;")

// ---------------------------------------------------------------------------
// batched elementwise pre-round to tf32 (rna); grid.y selects tensor
// ---------------------------------------------------------------------------
__global__ void preround3(const float* __restrict__ s0,
                          const float* __restrict__ s1,
                          const float* __restrict__ s2,
                          float* __restrict__ dst, int n4) {
    int i = blockIdx.x * blockDim.x + threadIdx.x;
    if (i >= n4) return;
    const float* src = (blockIdx.y == 0) ? s0 : (blockIdx.y == 1) ? s1 : s2;
    float4 v = ((const float4*)src)[i];
    uint4 u;
    u.x = f2tf(v.x); u.y = f2tf(v.y); u.z = f2tf(v.z); u.w = f2tf(v.w);
    ((uint4*)(dst + (size_t)blockIdx.y * n4 * 4))[i] = u;
}

__global__ void preround4(const float* __restrict__ s0,
                          const float* __restrict__ s1,
                          const float* __restrict__ s2,
                          const float* __restrict__ s3,
                          float* __restrict__ dst, int n4) {
    int i = blockIdx.x * blockDim.x + threadIdx.x;
    if (i >= n4) return;
    const float* src = (blockIdx.y == 0) ? s0 : (blockIdx.y == 1) ? s1
                     : (blockIdx.y == 2) ? s2 : s3;
    float4 v = ((const float4*)src)[i];
    uint4 u;
    u.x = f2tf(v.x); u.y = f2tf(v.y); u.z = f2tf(v.z); u.w = f2tf(v.w);
    ((uint4*)(dst + (size_t)blockIdx.y * n4 * 4))[i] = u;
}

// ---------------------------------------------------------------------------
// Fused QKV TC GEMM: grid.z selects (input, weight, bias, output).
// 128x64 tile, 8 warps (4m x 2n), cp.async double-buffered, k-tile 64.
// z==0 (Q): tf32(0.125*v), head-dim PERMUTED; z==1 (K): tf32(v), PERMUTED;
// z==2 (V): tf32(v), unpermuted.
// Permutation within each 8-col group: out[2(k&3)+(k>>2)] = in[k], so the
// attention kernel can load QK fragment pairs (k=t, k=t+4) as one LDS64.
// ---------------------------------------------------------------------------
__global__ void __launch_bounds__(256) gemm_qkv(
        const float* __restrict__ T, const float* __restrict__ W4,
        const float* __restrict__ bq, const float* __restrict__ bk,
        const float* __restrict__ bv,
        float* __restrict__ Qp, float* __restrict__ Kp, float* __restrict__ Vp) {
    extern __shared__ float sg[];
    float* Asb[2] = { sg,          sg + 8704 };            // 128*68 each
    float* Wsb[2] = { sg + 17408,  sg + 17408 + 4352 };    // 64*68 each

    const int M = B_ * S_, N = D_, K = D_;
    const int z = blockIdx.z;
    const float* A = T + (size_t)z * M * K;
    const float* W = W4 + (size_t)z * N * K;
    const float* bias = (z == 0) ? bq : (z == 1) ? bk : bv;
    float* C = (z == 0) ? Qp : (z == 1) ? Kp : Vp;

    const int tid = threadIdx.x, lane = tid & 31, w = tid >> 5;
    const int mw = w >> 1, nw = w & 1, g = lane >> 2, t = lane & 3;
    const int m0 = blockIdx.x * 128, n0 = blockIdx.y * 64;

    float acc[2][4][4] = {};

#define GSTAGE(k0, bufi)                                                       \
    {                                                                          \
        _Pragma("unroll")                                                      \
        for (int r = 0; r < 8; r++) {                                          \
            int idx = tid + r * 256, rr = idx >> 4, cc = idx & 15;             \
            cpa16(cvs(&Asb[bufi][rr * 68 + cc * 4]),                           \
                  &A[(size_t)(m0 + rr) * K + (k0) + cc * 4]);                  \
        }                                                                      \
        _Pragma("unroll")                                                      \
        for (int r = 0; r < 4; r++) {                                          \
            int idx = tid + r * 256, rr = idx >> 4, cc = idx & 15;             \
            cpa16(cvs(&Wsb[bufi][rr * 68 + cc * 4]),                           \
                  &W[(size_t)(n0 + rr) * K + (k0) + cc * 4]);                  \
        }                                                                      \
    }

    GSTAGE(0, 0); CPCOMMIT;
    const int NT = K / 64;
    for (int kt = 0; kt < NT; kt++) {
        CPWAIT0;
        __syncthreads();
        if (kt + 1 < NT) { GSTAGE((kt + 1) * 64, (kt + 1) & 1); CPCOMMIT; }
        const uint32_t* Au = (const uint32_t*)Asb[kt & 1];
        const uint32_t* Wu = (const uint32_t*)Wsb[kt & 1];
#pragma unroll
        for (int k8 = 0; k8 < 8; k8++) {
            uint32_t a[2][4];
#pragma unroll
            for (int mm = 0; mm < 2; mm++) {
                int ar = (mw * 32 + mm * 16 + g) * 68 + t + 8 * k8;
                a[mm][0] = Au[ar];     a[mm][1] = Au[ar + 8 * 68];
                a[mm][2] = Au[ar + 4]; a[mm][3] = Au[ar + 8 * 68 + 4];
            }
#pragma unroll
            for (int nf = 0; nf < 4; nf++) {
                int br = (nw * 32 + nf * 8 + g) * 68 + t + 8 * k8;
                uint32_t b0 = Wu[br], b1 = Wu[br + 4];
                mma8(acc[0][nf], a[0], b0, b1);
                mma8(acc[1][nf], a[1], b0, b1);
            }
        }
    }

    const float sc = (z == 0) ? 0.125f : 1.0f;
    const bool perm = (z < 2);
#pragma unroll
    for (int mm = 0; mm < 2; mm++) {
        int mrow = m0 + mw * 32 + mm * 16 + g;
#pragma unroll
        for (int nf = 0; nf < 4; nf++) {
            int base8 = n0 + nw * 32 + nf * 8;
            float b0 = bias[base8 + 2 * t], b1 = bias[base8 + 2 * t + 1];
            float v0 = __uint_as_float(f2tf((acc[mm][nf][0] + b0) * sc));
            float v1 = __uint_as_float(f2tf((acc[mm][nf][1] + b1) * sc));
            float v2 = __uint_as_float(f2tf((acc[mm][nf][2] + b0) * sc));
            float v3 = __uint_as_float(f2tf((acc[mm][nf][3] + b1) * sc));
            if (perm) {
                int p0 = base8 + (t & 1) * 4 + (t >> 1);  // perm(2t)
                C[(size_t)mrow * N + p0]     = v0;
                C[(size_t)mrow * N + p0 + 2] = v1;        // perm(2t+1)
                C[(size_t)(mrow + 8) * N + p0]     = v2;
                C[(size_t)(mrow + 8) * N + p0 + 2] = v3;
            } else {
                int n = base8 + 2 * t;
                *(float2*)&C[(size_t)mrow * N + n] = make_float2(v0, v1);
                *(float2*)&C[(size_t)(mrow + 8) * N + n] = make_float2(v2, v3);
            }
        }
    }
}

// ---------------------------------------------------------------------------
// O-projection GEMM (raw fp32 out, streaming store): identical inner loop.
// ---------------------------------------------------------------------------
__global__ void __launch_bounds__(256) gemm_o(const float* __restrict__ A,
                                              const float* __restrict__ W,
                                              const float* __restrict__ bias,
                                              float* __restrict__ C,
                                              int M, int N, int K) {
    extern __shared__ float sg[];
    float* Asb[2] = { sg,          sg + 8704 };
    float* Wsb[2] = { sg + 17408,  sg + 17408 + 4352 };

    const int tid = threadIdx.x, lane = tid & 31, w = tid >> 5;
    const int mw = w >> 1, nw = w & 1, g = lane >> 2, t = lane & 3;
    const int m0 = blockIdx.x * 128, n0 = blockIdx.y * 64;

    float acc[2][4][4] = {};

    GSTAGE(0, 0); CPCOMMIT;
    const int NT = K / 64;
    for (int kt = 0; kt < NT; kt++) {
        CPWAIT0;
        __syncthreads();
        if (kt + 1 < NT) { GSTAGE((kt + 1) * 64, (kt + 1) & 1); CPCOMMIT; }
        const uint32_t* Au = (const uint32_t*)Asb[kt & 1];
        const uint32_t* Wu = (const uint32_t*)Wsb[kt & 1];
#pragma unroll
        for (int k8 = 0; k8 < 8; k8++) {
            uint32_t a[2][4];
#pragma unroll
            for (int mm = 0; mm < 2; mm++) {
                int ar = (mw * 32 + mm * 16 + g) * 68 + t + 8 * k8;
                a[mm][0] = Au[ar];     a[mm][1] = Au[ar + 8 * 68];
                a[mm][2] = Au[ar + 4]; a[mm][3] = Au[ar + 8 * 68 + 4];
            }
#pragma unroll
            for (int nf = 0; nf < 4; nf++) {
                int br = (nw * 32 + nf * 8 + g) * 68 + t + 8 * k8;
                uint32_t b0 = Wu[br], b1 = Wu[br + 4];
                mma8(acc[0][nf], a[0], b0, b1);
                mma8(acc[1][nf], a[1], b0, b1);
            }
        }
    }

#pragma unroll
    for (int mm = 0; mm < 2; mm++) {
        int mrow = m0 + mw * 32 + mm * 16 + g;
#pragma unroll
        for (int nf = 0; nf < 4; nf++) {
            int n = n0 + nw * 32 + nf * 8 + 2 * t;
            float b0 = bias[n], b1 = bias[n + 1];
            __stcs((float2*)&C[(size_t)mrow * N + n],
                   make_float2(acc[mm][nf][0] + b0, acc[mm][nf][1] + b1));
            __stcs((float2*)&C[(size_t)(mrow + 8) * N + n],
                   make_float2(acc[mm][nf][2] + b0, acc[mm][nf][3] + b1));
        }
    }
}

// ---------------------------------------------------------------------------
// TC flash attention — R13 structure; Q/K head-dim permuted so QK fragments
// load as conflict-free LDS64 pairs (Q,K smem stride 72).
// ---------------------------------------------------------------------------
#define STRK 72
#define STRV 72

__global__ void __launch_bounds__(256, 2)
attn_tc(const float* __restrict__ Qg, const float* __restrict__ Kg,
        const float* __restrict__ Vg, float* __restrict__ Pout,
        float* __restrict__ Oout) {
    extern __shared__ float sm[];
    float* Ksb[2] = { sm,                 sm + 64 * STRK };
    float* Vsb[2] = { sm + 2 * 64 * STRK, sm + 2 * 64 * STRK + 64 * STRV };
    float* Qs = sm + 2 * 64 * STRK + 2 * 64 * STRV;  // 64*72 = 4608 (Q / PT)
    uint2* PT = (uint2*)Qs;                          // P: [col*36 + pair]
    float* Ls = Qs + 4608;                           // 256 floats
    const uint32_t* Qu = (const uint32_t*)Qs;

    const int tid = threadIdx.x, lane = tid & 31, w = tid >> 5;
    const int mw = w & 1, nw = w >> 1, g = lane >> 2, t = lane & 3;
    const int q0 = blockIdx.x * 64, h = blockIdx.y, b = blockIdx.z;
    const size_t qbase = ((size_t)b * S_ + q0) * D_ + h * DK_;
    const size_t kvbase = (size_t)b * S_ * D_ + h * DK_;

#define KSTAGE(jt, bufi)                                                       \
    {                                                                          \
        _Pragma("unroll")                                                      \
        for (int r = 0; r < 4; r++) {                                          \
            int idx = tid + r * 256, rr = idx >> 4, cc = idx & 15;             \
            cpa16(cvs(&Ksb[bufi][rr * STRK + cc * 4]),                         \
                  &Kg[kvbase + (size_t)((jt) * 64 + rr) * D_ + cc * 4]);       \
        }                                                                      \
    }
#define VSTAGE(jt, bufi)                                                       \
    {                                                                          \
        _Pragma("unroll")                                                      \
        for (int r = 0; r < 4; r++) {                                          \
            int idx = tid + r * 256, rr = idx >> 4, cc = idx & 15;             \
            cpa16(cvs(&Vsb[bufi][rr * STRV + cc * 4]),                         \
                  &Vg[kvbase + (size_t)((jt) * 64 + rr) * D_ + cc * 4]);       \
        }                                                                      \
    }

    // stage Q (tf32, scaled, head-dim permuted); pull A-fragments via LDS64
#pragma unroll
    for (int r = 0; r < 4; r++) {
        int idx = tid + r * 256, rr = idx >> 4, cc = idx & 15;
        *(float4*)&Qs[rr * STRK + cc * 4] =
            *(const float4*)&Qg[qbase + (size_t)rr * D_ + cc * 4];
    }
    __syncthreads();
    uint32_t qa[2][8][4];
#pragma unroll
    for (int mm = 0; mm < 2; mm++) {
        int ar = (mw * 32 + mm * 16 + g) * STRK + 2 * t;
#pragma unroll
        for (int k8 = 0; k8 < 8; k8++) {
            uint2 q02 = *(const uint2*)&Qu[ar + 8 * k8];
            uint2 q13 = *(const uint2*)&Qu[ar + 8 * STRK + 8 * k8];
            qa[mm][k8][0] = q02.x; qa[mm][k8][1] = q13.x;
            qa[mm][k8][2] = q02.y; qa[mm][k8][3] = q13.y;
        }
    }

    // ---------------- pass 1: rowsums of exp(scores) ----------------
    KSTAGE(0, 0); CPCOMMIT;
    float ls[2][2] = {};
    for (int jt = 0; jt < S_ / 64; jt++) {
        CPWAIT0;
        __syncthreads();
        if (jt + 1 < S_ / 64) { KSTAGE(jt + 1, (jt + 1) & 1); CPCOMMIT; }
        const uint32_t* Ku = (const uint32_t*)Ksb[jt & 1];
        float c[2][2][4] = {};
#pragma unroll
        for (int k8 = 0; k8 < 8; k8++) {
#pragma unroll
            for (int nf = 0; nf < 2; nf++) {
                int br = (nw * 16 + nf * 8 + g) * STRK + 2 * t + 8 * k8;
                uint2 bb = *(const uint2*)&Ku[br];
                mma8(c[0][nf], qa[0][k8], bb.x, bb.y);
                mma8(c[1][nf], qa[1][k8], bb.x, bb.y);
            }
        }
#pragma unroll
        for (int mm = 0; mm < 2; mm++)
#pragma unroll
            for (int nf = 0; nf < 2; nf++) {
                ls[mm][0] += __expf(c[mm][nf][0]) + __expf(c[mm][nf][1]);
                ls[mm][1] += __expf(c[mm][nf][2]) + __expf(c[mm][nf][3]);
            }
    }
#pragma unroll
    for (int mm = 0; mm < 2; mm++)
#pragma unroll
        for (int hh = 0; hh < 2; hh++) {
            ls[mm][hh] += __shfl_xor_sync(~0u, ls[mm][hh], 1);
            ls[mm][hh] += __shfl_xor_sync(~0u, ls[mm][hh], 2);
        }
    if (t == 0) {
#pragma unroll
        for (int mm = 0; mm < 2; mm++) {
            Ls[nw * 64 + mw * 32 + mm * 16 + g]     = ls[mm][0];
            Ls[nw * 64 + mw * 32 + mm * 16 + 8 + g] = ls[mm][1];
        }
    }
    KSTAGE(0, 0); VSTAGE(0, 0); CPCOMMIT;
    __syncthreads();
    float linv[2][2];
#pragma unroll
    for (int mm = 0; mm < 2; mm++) {
        int r0 = mw * 32 + mm * 16 + g;
        linv[mm][0] = 1.f / (Ls[r0] + Ls[64 + r0] + Ls[128 + r0] + Ls[192 + r0]);
        int r1 = r0 + 8;
        linv[mm][1] = 1.f / (Ls[r1] + Ls[64 + r1] + Ls[128 + r1] + Ls[192 + r1]);
    }
    __syncthreads();  // Qs fragments consumed; PT region now owned by pass 2

    // ---------------- pass 2: P out + P@V ----------------
    float out[2][2][4] = {};
    for (int jt = 0; jt < S_ / 64; jt++) {
        CPWAIT0;
        __syncthreads();
        if (jt + 1 < S_ / 64) {
            KSTAGE(jt + 1, (jt + 1) & 1); VSTAGE(jt + 1, (jt + 1) & 1); CPCOMMIT;
        }
        const uint32_t* Ku = (const uint32_t*)Ksb[jt & 1];
        const uint32_t* Vu = (const uint32_t*)Vsb[jt & 1];
        float c[2][2][4] = {};
#pragma unroll
        for (int k8 = 0; k8 < 8; k8++) {
#pragma unroll
            for (int nf = 0; nf < 2; nf++) {
                int br = (nw * 16 + nf * 8 + g) * STRK + 2 * t + 8 * k8;
                uint2 bb = *(const uint2*)&Ku[br];
                mma8(c[0][nf], qa[0][k8], bb.x, bb.y);
                mma8(c[1][nf], qa[1][k8], bb.x, bb.y);
            }
        }
        // normalized P -> gmem (streaming); tf32 P -> transposed smem tile
#pragma unroll
        for (int mm = 0; mm < 2; mm++) {
            int rowg = mw * 32 + mm * 16 + g;
            int pi = 16 * mw + 8 * mm + g;
            size_t gp = ((size_t)(b * H_ + h) * S_ + (q0 + rowg)) * S_ +
                        jt * 64 + nw * 16 + 2 * t;
#pragma unroll
            for (int nf = 0; nf < 2; nf++) {
                float p0 = __expf(c[mm][nf][0]) * linv[mm][0];
                float p1 = __expf(c[mm][nf][1]) * linv[mm][0];
                float p2 = __expf(c[mm][nf][2]) * linv[mm][1];
                float p3 = __expf(c[mm][nf][3]) * linv[mm][1];
                __stcs((float2*)&Pout[gp + nf * 8], make_float2(p0, p1));
                __stcs((float2*)&Pout[gp + nf * 8 + (size_t)8 * S_],
                       make_float2(p2, p3));
                int c0 = nw * 16 + nf * 8 + 2 * t;
                PT[c0 * 36 + pi] = make_uint2(f2tf(p0), f2tf(p2));
                PT[(c0 + 1) * 36 + pi] = make_uint2(f2tf(p1), f2tf(p3));
            }
        }
        __syncthreads();
        // P @ V  (pa via conflict-free LDS64)
#pragma unroll
        for (int k8 = 0; k8 < 8; k8++) {
            int ca = t + 8 * k8, cb = ca + 4;
            uint2 u0 = PT[ca * 36 + 16 * mw + g];
            uint2 u1 = PT[cb * 36 + 16 * mw + g];
            uint2 u2 = PT[ca * 36 + 16 * mw + 8 + g];
            uint2 u3 = PT[cb * 36 + 16 * mw + 8 + g];
            uint32_t pa0[4] = { u0.x, u0.y, u1.x, u1.y };
            uint32_t pa1[4] = { u2.x, u2.y, u3.x, u3.y };
#pragma unroll
            for (int nf = 0; nf < 2; nf++) {
                int n = nw * 16 + nf * 8 + g;
                uint32_t b0 = Vu[(8 * k8 + t) * STRV + n];
                uint32_t b1 = Vu[(8 * k8 + t + 4) * STRV + n];
                mma8(out[0][nf], pa0, b0, b1);
                mma8(out[1][nf], pa1, b0, b1);
            }
        }
        __syncthreads();
    }

    // epilogue: AO in [B,S,D], tf32-rounded for the O-GEMM (unpermuted)
#pragma unroll
    for (int mm = 0; mm < 2; mm++) {
        int row = q0 + mw * 32 + mm * 16 + g;
#pragma unroll
        for (int nf = 0; nf < 2; nf++) {
            int dk = h * DK_ + nw * 16 + nf * 8 + 2 * t;
            *(float2*)&Oout[((size_t)b * S_ + row) * D_ + dk] =
                make_float2(__uint_as_float(f2tf(out[mm][nf][0])),
                            __uint_as_float(f2tf(out[mm][nf][1])));
            *(float2*)&Oout[((size_t)b * S_ + row + 8) * D_ + dk] =
                make_float2(__uint_as_float(f2tf(out[mm][nf][2])),
                            __uint_as_float(f2tf(out[mm][nf][3])));
        }
    }
}

// ---------------------------------------------------------------------------
extern "C" void kernel_launch(void* const* d_in, const int* in_sizes, int n_in,
                              void* d_out, int out_size) {
    const float* query = (const float*)d_in[0];
    const float* key   = (const float*)d_in[1];
    const float* value = (const float*)d_in[2];
    const float* Wq = (const float*)d_in[3];
    const float* bq = (const float*)d_in[4];
    const float* Wk = (const float*)d_in[5];
    const float* bk = (const float*)d_in[6];
    const float* Wv = (const float*)d_in[7];
    const float* bv = (const float*)d_in[8];
    const float* Wo = (const float*)d_in[9];
    const float* bo = (const float*)d_in[10];

    float* out_main = (float*)d_out;
    float* out_attn = (float*)d_out + (size_t)B_ * S_ * D_;

    float* Qp;  cudaGetSymbolAddress((void**)&Qp, g_Q);
    float* Kp;  cudaGetSymbolAddress((void**)&Kp, g_K);
    float* Vp;  cudaGetSymbolAddress((void**)&Vp, g_V);
    float* AOp; cudaGetSymbolAddress((void**)&AOp, g_AO);
    float* Tp;  cudaGetSymbolAddress((void**)&Tp, g_T);
    float* Wp;  cudaGetSymbolAddress((void**)&Wp, g_W4);

    const size_t NX = (size_t)B_ * S_ * D_;   // 6291456
    const size_t NW = (size_t)D_ * D_;        // 589824

    preround3<<<dim3((int)(NX / 4 + 255) / 256, 3), 256>>>(
        query, key, value, Tp, (int)(NX / 4));
    preround4<<<dim3((int)(NW / 4 + 255) / 256, 4), 256>>>(
        Wq, Wk, Wv, Wo, Wp, (int)(NW / 4));

    const int M = B_ * S_;
    const int gsmem = (2 * 8704 + 2 * 4352) * 4;   // 104448 B
    cudaFuncSetAttribute(gemm_qkv,
                         cudaFuncAttributeMaxDynamicSharedMemorySize, gsmem);
    cudaFuncSetAttribute(gemm_o,
                         cudaFuncAttributeMaxDynamicSharedMemorySize, gsmem);
    const int asmem = (2 * 64 * STRK + 2 * 64 * STRV + 4608 + 256) * 4;  // 93184 B
    cudaFuncSetAttribute(attn_tc,
                         cudaFuncAttributeMaxDynamicSharedMemorySize, asmem);

    gemm_qkv<<<dim3(M / 128, D_ / 64, 3), 256, gsmem>>>(
        Tp, Wp, bq, bk, bv, Qp, Kp, Vp);

    attn_tc<<<dim3(S_ / 64, H_, B_), 256, asmem>>>(Qp, Kp, Vp, out_attn, AOp);

    gemm_o<<<dim3(M / 128, D_ / 64), 256, gsmem>>>(
        AOp, Wp + 3 * NW, bo, out_main, M, D_, D_);
}